// round 4
// baseline (speedup 1.0000x reference)
#include <cuda_runtime.h>

// Problem constants
#define NP    196          // patches per image
#define NCG   49           // NP/4 column groups
#define HID   32
#define NCLS  10
#define TSQRT 0.894427191f // sqrt(0.8)

__device__ __forceinline__ float dot4(float4 a, float4 b) {
    return a.x * b.x + a.y * b.y + a.z * b.z + a.w * b.w;
}

// fid = dot^2 >= 0.8  <=>  |dot| >= sqrt(0.8); FSETP applies |.| for free
__device__ __forceinline__ float classify(float d) {
    return (fabsf(d) >= TSQRT) ? 1.0f : 0.0f;
}

__global__ __launch_bounds__(256, 5)
void quanv_graph_kernel(const float* __restrict__ x,
                        const float* __restrict__ W1,
                        const float* __restrict__ b1,
                        const float* __restrict__ W2,
                        const float* __restrict__ b2,
                        float* __restrict__ out,
                        float* __restrict__ adj)
{
    __shared__ float4 an_s[NP];   // normalized vectors
    __shared__ float4 vec_s[NP];  // raw vectors (for pooling)

    const int b   = blockIdx.x;
    const int tid = threadIdx.x;

    // ---- Phase 1: per-patch quantum-circuit expectation values ----
    if (tid < NP) {
        const float4 p = reinterpret_cast<const float4*>(x)[(size_t)b * NP + tid];
        float c0 = cosf(p.x + 0.5f);
        float c1 = c0 * cosf(p.y + 0.5f);
        float c2 = c1 * cosf(p.z + 0.5f);
        float c3 = c2 * cosf(p.w + 0.5f);
        vec_s[tid] = make_float4(c0, c1, c2, c3);
        float n   = sqrtf(c0 * c0 + c1 * c1 + c2 * c2 + c3 * c3);
        float inv = 1.0f / (n + 1e-12f);
        an_s[tid] = make_float4(c0 * inv, c1 * inv, c2 * inv, c3 * inv);
    }
    __syncthreads();

    const int warp = tid >> 5;
    const int lane = tid & 31;
    float* __restrict__ adjb = adj + (size_t)b * (NP * NP);

    // ---- MLP head: warp 7, lanes 0..9 (redundant per-lane, deterministic) ----
    if (warp == 7 && lane < NCLS) {
        float px = 0.f, py = 0.f, pz = 0.f, pw = 0.f;
        #pragma unroll 4
        for (int p = 0; p < NP; ++p) {
            float4 v = vec_s[p];   // same address across lanes -> smem broadcast
            px += v.x; py += v.y; pz += v.z; pw += v.w;
        }
        const float s = 1.0f / (float)NP;
        px *= s; py *= s; pz *= s; pw *= s;
        float acc = b2[lane];
        #pragma unroll 4
        for (int h = 0; h < HID; ++h) {
            float hh = b1[h] + px * W1[h * 4 + 0] + py * W1[h * 4 + 1]
                             + pz * W1[h * 4 + 2] + pw * W1[h * 4 + 3];
            acc += hh * W2[lane * HID + h];
        }
        out[(size_t)b * NCLS + lane] = acc;
    }

    // ---- Phase 2a: MAIN — columns 0..127 (cg = lane, all 32 lanes busy) ----
    // Each lane holds its column group's 4 vectors in registers; inside the
    // loop the only smem reads are warp-uniform broadcasts a0..a3.
    {
        const float4 u0 = an_s[4 * lane + 0];
        const float4 u1 = an_s[4 * lane + 1];
        const float4 u2 = an_s[4 * lane + 2];
        const float4 u3 = an_s[4 * lane + 3];

        for (int rg = warp; rg < NCG; rg += 8) {
            const float4 a0 = an_s[4 * rg + 0];   // warp-uniform -> broadcast
            const float4 a1 = an_s[4 * rg + 1];
            const float4 a2 = an_s[4 * rg + 2];
            const float4 a3 = an_s[4 * rg + 3];

            float4 r0 = make_float4(classify(dot4(a0, u0)), classify(dot4(a0, u1)),
                                    classify(dot4(a0, u2)), classify(dot4(a0, u3)));
            float4 r1 = make_float4(classify(dot4(a1, u0)), classify(dot4(a1, u1)),
                                    classify(dot4(a1, u2)), classify(dot4(a1, u3)));
            float4 r2 = make_float4(classify(dot4(a2, u0)), classify(dot4(a2, u1)),
                                    classify(dot4(a2, u2)), classify(dot4(a2, u3)));
            float4 r3 = make_float4(classify(dot4(a3, u0)), classify(dot4(a3, u1)),
                                    classify(dot4(a3, u2)), classify(dot4(a3, u3)));
            if (rg == lane) {   // self-edge diagonal lives in this lane's block
                r0.x = 0.f; r1.y = 0.f; r2.z = 0.f; r3.w = 0.f;
            }
            __stcs(reinterpret_cast<float4*>(adjb + (size_t)(4 * rg + 0) * NP) + lane, r0);
            __stcs(reinterpret_cast<float4*>(adjb + (size_t)(4 * rg + 1) * NP) + lane, r1);
            __stcs(reinterpret_cast<float4*>(adjb + (size_t)(4 * rg + 2) * NP) + lane, r2);
            __stcs(reinterpret_cast<float4*>(adjb + (size_t)(4 * rg + 3) * NP) + lane, r3);
        }
    }

    // ---- Phase 2b: TAIL — columns 128..195 (17 groups x 196 rows) ----
    // 255 threads: thread t owns fixed column group cg = 32 + t%17 (w-vectors
    // in registers, loaded once — reuses the now-dead u registers), and rows
    // row0 = t/17, row0+15, ... Each iteration: 1 near-broadcast LDS (2 row
    // addresses per warp), 16 FMA, 1 contiguous STG.128 run per 17 lanes.
    if (tid < 255) {
        const int cgl  = tid % 17;          // 0..16
        const int cg   = 32 + cgl;          // 32..48
        const int row0 = tid / 17;          // 0..14

        const float4 w0 = an_s[4 * cg + 0];
        const float4 w1 = an_s[4 * cg + 1];
        const float4 w2 = an_s[4 * cg + 2];
        const float4 w3 = an_s[4 * cg + 3];

        for (int row = row0; row < NP; row += 15) {
            const float4 a = an_s[row];
            float4 r = make_float4(classify(dot4(a, w0)), classify(dot4(a, w1)),
                                   classify(dot4(a, w2)), classify(dot4(a, w3)));
            if ((row >> 2) == cg) {         // diagonal falls in this group
                if      ((row & 3) == 0) r.x = 0.f;
                else if ((row & 3) == 1) r.y = 0.f;
                else if ((row & 3) == 2) r.z = 0.f;
                else                     r.w = 0.f;
            }
            __stcs(reinterpret_cast<float4*>(adjb + (size_t)row * NP) + cg, r);
        }
    }
}

extern "C" void kernel_launch(void* const* d_in, const int* in_sizes, int n_in,
                              void* d_out, int out_size)
{
    const float* x  = (const float*)d_in[0];   // [B,1,28,28]
    const float* W1 = (const float*)d_in[1];   // [32,4]
    const float* b1 = (const float*)d_in[2];   // [32]
    const float* W2 = (const float*)d_in[3];   // [10,32]
    const float* b2 = (const float*)d_in[4];   // [10]

    const int B = in_sizes[0] / 784;           // 4096

    float* out = (float*)d_out;                // [B,10] first
    float* adj = (float*)d_out + (size_t)B * NCLS;  // then [B,196,196]

    quanv_graph_kernel<<<B, 256>>>(x, W1, b1, W2, b2, out, adj);
}

// round 5
// speedup vs baseline: 1.3194x; 1.3194x over previous
#include <cuda_runtime.h>

// Problem constants
#define NP    196          // patches per image
#define NCG   49           // NP/4 column groups
#define HID   32
#define NCLS  10
#define TSQRT 0.894427191f // sqrt(0.8)

__device__ __forceinline__ float dot4(float4 a, float4 b) {
    return a.x * b.x + a.y * b.y + a.z * b.z + a.w * b.w;
}

// fid = dot^2 >= 0.8  <=>  |dot| >= sqrt(0.8); FSETP applies |.| for free
__device__ __forceinline__ float classify(float d) {
    return (fabsf(d) >= TSQRT) ? 1.0f : 0.0f;
}

__global__ __launch_bounds__(256, 4)
void quanv_graph_kernel(const float* __restrict__ x,
                        const float* __restrict__ W1,
                        const float* __restrict__ b1,
                        const float* __restrict__ W2,
                        const float* __restrict__ b2,
                        float* __restrict__ out,
                        float* __restrict__ adj)
{
    __shared__ float4 an_s[NP];   // normalized vectors
    __shared__ float4 vec_s[NP];  // raw vectors (for pooling)

    const int b   = blockIdx.x;
    const int tid = threadIdx.x;

    // ---- Phase 1: per-patch quantum-circuit expectation values ----
    if (tid < NP) {
        const float4 p = reinterpret_cast<const float4*>(x)[(size_t)b * NP + tid];
        float c0 = cosf(p.x + 0.5f);
        float c1 = c0 * cosf(p.y + 0.5f);
        float c2 = c1 * cosf(p.z + 0.5f);
        float c3 = c2 * cosf(p.w + 0.5f);
        vec_s[tid] = make_float4(c0, c1, c2, c3);
        float n   = sqrtf(c0 * c0 + c1 * c1 + c2 * c2 + c3 * c3);
        float inv = 1.0f / (n + 1e-12f);
        an_s[tid] = make_float4(c0 * inv, c1 * inv, c2 * inv, c3 * inv);
    }
    __syncthreads();

    const int warp = tid >> 5;
    const int lane = tid & 31;
    float* __restrict__ adjb = adj + (size_t)b * (NP * NP);

    // ---- MLP head: warp 7, lanes 0..9 (redundant per-lane, deterministic) ----
    if (warp == 7 && lane < NCLS) {
        float px = 0.f, py = 0.f, pz = 0.f, pw = 0.f;
        #pragma unroll 4
        for (int p = 0; p < NP; ++p) {
            float4 v = vec_s[p];   // same address across lanes -> smem broadcast
            px += v.x; py += v.y; pz += v.z; pw += v.w;
        }
        const float s = 1.0f / (float)NP;
        px *= s; py *= s; pz *= s; pw *= s;
        float acc = b2[lane];
        #pragma unroll
        for (int h = 0; h < HID; ++h) {
            float hh = b1[h] + px * W1[h * 4 + 0] + py * W1[h * 4 + 1]
                             + pz * W1[h * 4 + 2] + pw * W1[h * 4 + 3];
            acc += hh * W2[lane * HID + h];
        }
        out[(size_t)b * NCLS + lane] = acc;
    }

    // ---- Phase 2: adjacency (R2 structure) ----
    // Lane owns two fixed column groups (cg0 = lane, cg1 = lane + 32) held in
    // registers across the whole rg loop; inside the loop only warp-uniform
    // broadcast LDS for the row vectors. Plain write-back stores so L2 can
    // merge the 784B-row partial sectors to full before eviction.
    const int cg0 = lane;            // always < 49
    const int cg1 = lane + 32;       // valid only for lane < 17
    const bool has1 = (cg1 < NCG);

    const float4 u0 = an_s[4 * cg0 + 0];
    const float4 u1 = an_s[4 * cg0 + 1];
    const float4 u2 = an_s[4 * cg0 + 2];
    const float4 u3 = an_s[4 * cg0 + 3];

    float4 w0, w1, w2, w3;
    {
        const int c = has1 ? cg1 : 0;   // dummy-load group 0 for inactive lanes
        w0 = an_s[4 * c + 0];
        w1 = an_s[4 * c + 1];
        w2 = an_s[4 * c + 2];
        w3 = an_s[4 * c + 3];
    }

    for (int rg = warp; rg < NCG; rg += 8) {
        const float4 a0 = an_s[4 * rg + 0];   // warp-uniform -> broadcast
        const float4 a1 = an_s[4 * rg + 1];
        const float4 a2 = an_s[4 * rg + 2];
        const float4 a3 = an_s[4 * rg + 3];

        // --- columns cg0 (all 32 lanes): cols [0,128) of each row ---
        {
            float4 r0 = make_float4(classify(dot4(a0, u0)), classify(dot4(a0, u1)),
                                    classify(dot4(a0, u2)), classify(dot4(a0, u3)));
            float4 r1 = make_float4(classify(dot4(a1, u0)), classify(dot4(a1, u1)),
                                    classify(dot4(a1, u2)), classify(dot4(a1, u3)));
            float4 r2 = make_float4(classify(dot4(a2, u0)), classify(dot4(a2, u1)),
                                    classify(dot4(a2, u2)), classify(dot4(a2, u3)));
            float4 r3 = make_float4(classify(dot4(a3, u0)), classify(dot4(a3, u1)),
                                    classify(dot4(a3, u2)), classify(dot4(a3, u3)));
            if (rg == cg0) {
                r0.x = 0.f; r1.y = 0.f; r2.z = 0.f; r3.w = 0.f;
            }
            reinterpret_cast<float4*>(adjb + (size_t)(4 * rg + 0) * NP)[cg0] = r0;
            reinterpret_cast<float4*>(adjb + (size_t)(4 * rg + 1) * NP)[cg0] = r1;
            reinterpret_cast<float4*>(adjb + (size_t)(4 * rg + 2) * NP)[cg0] = r2;
            reinterpret_cast<float4*>(adjb + (size_t)(4 * rg + 3) * NP)[cg0] = r3;
        }

        // --- columns cg1 (lanes 0..16): cols [128,196) of each row ---
        if (has1) {
            float4 r0 = make_float4(classify(dot4(a0, w0)), classify(dot4(a0, w1)),
                                    classify(dot4(a0, w2)), classify(dot4(a0, w3)));
            float4 r1 = make_float4(classify(dot4(a1, w0)), classify(dot4(a1, w1)),
                                    classify(dot4(a1, w2)), classify(dot4(a1, w3)));
            float4 r2 = make_float4(classify(dot4(a2, w0)), classify(dot4(a2, w1)),
                                    classify(dot4(a2, w2)), classify(dot4(a2, w3)));
            float4 r3 = make_float4(classify(dot4(a3, w0)), classify(dot4(a3, w1)),
                                    classify(dot4(a3, w2)), classify(dot4(a3, w3)));
            if (rg == cg1) {
                r0.x = 0.f; r1.y = 0.f; r2.z = 0.f; r3.w = 0.f;
            }
            reinterpret_cast<float4*>(adjb + (size_t)(4 * rg + 0) * NP)[cg1] = r0;
            reinterpret_cast<float4*>(adjb + (size_t)(4 * rg + 1) * NP)[cg1] = r1;
            reinterpret_cast<float4*>(adjb + (size_t)(4 * rg + 2) * NP)[cg1] = r2;
            reinterpret_cast<float4*>(adjb + (size_t)(4 * rg + 3) * NP)[cg1] = r3;
        }
    }
}

extern "C" void kernel_launch(void* const* d_in, const int* in_sizes, int n_in,
                              void* d_out, int out_size)
{
    const float* x  = (const float*)d_in[0];   // [B,1,28,28]
    const float* W1 = (const float*)d_in[1];   // [32,4]
    const float* b1 = (const float*)d_in[2];   // [32]
    const float* W2 = (const float*)d_in[3];   // [10,32]
    const float* b2 = (const float*)d_in[4];   // [10]

    const int B = in_sizes[0] / 784;           // 4096

    float* out = (float*)d_out;                // [B,10] first
    float* adj = (float*)d_out + (size_t)B * NCLS;  // then [B,196,196]

    quanv_graph_kernel<<<B, 256>>>(x, W1, b1, W2, b2, out, adj);
}

// round 6
// speedup vs baseline: 1.4596x; 1.1063x over previous
#include <cuda_runtime.h>

// Problem constants
#define NP    196           // patches per image
#define NCG   49            // NP/4 column groups
#define NF4   (NP * NCG)    // 9604 float4 elements in one adj matrix
#define TPB   392           // 8 * 49 threads: stride keeps cg fixed per thread
#define HID   32
#define NCLS  10
#define TSQRT 0.894427191f  // sqrt(0.8)

__device__ __forceinline__ float dot4(float4 a, float4 b) {
    return a.x * b.x + a.y * b.y + a.z * b.z + a.w * b.w;
}

// fid = dot^2 >= 0.8  <=>  |dot| >= sqrt(0.8); FSETP applies |.| for free
__device__ __forceinline__ float classify(float d) {
    return (fabsf(d) >= TSQRT) ? 1.0f : 0.0f;
}

__global__ __launch_bounds__(TPB, 2)
void quanv_graph_kernel(const float* __restrict__ x,
                        const float* __restrict__ W1,
                        const float* __restrict__ b1,
                        const float* __restrict__ W2,
                        const float* __restrict__ b2,
                        float* __restrict__ out,
                        float* __restrict__ adj)
{
    __shared__ float4 an_s[NP];   // normalized vectors
    __shared__ float4 vec_s[NP];  // raw vectors (for pooling)

    const int b   = blockIdx.x;
    const int tid = threadIdx.x;

    // ---- Phase 1: per-patch quantum-circuit expectation values ----
    if (tid < NP) {
        const float4 p = reinterpret_cast<const float4*>(x)[(size_t)b * NP + tid];
        float c0 = cosf(p.x + 0.5f);
        float c1 = c0 * cosf(p.y + 0.5f);
        float c2 = c1 * cosf(p.z + 0.5f);
        float c3 = c2 * cosf(p.w + 0.5f);
        vec_s[tid] = make_float4(c0, c1, c2, c3);
        float n   = sqrtf(c0 * c0 + c1 * c1 + c2 * c2 + c3 * c3);
        float inv = 1.0f / (n + 1e-12f);
        an_s[tid] = make_float4(c0 * inv, c1 * inv, c2 * inv, c3 * inv);
    }
    __syncthreads();

    // ---- MLP head: threads 0..9, one class each (redundant pooling) ----
    if (tid < NCLS) {
        float px = 0.f, py = 0.f, pz = 0.f, pw = 0.f;
        #pragma unroll 4
        for (int p = 0; p < NP; ++p) {
            float4 v = vec_s[p];   // same address across threads -> broadcast
            px += v.x; py += v.y; pz += v.z; pw += v.w;
        }
        const float s = 1.0f / (float)NP;
        px *= s; py *= s; pz *= s; pw *= s;
        float acc = b2[tid];
        #pragma unroll 4
        for (int h = 0; h < HID; ++h) {
            float hh = b1[h] + px * W1[h * 4 + 0] + py * W1[h * 4 + 1]
                             + pz * W1[h * 4 + 2] + pw * W1[h * 4 + 3];
            acc += hh * W2[tid * HID + h];
        }
        out[(size_t)b * NCLS + tid] = acc;
    }

    // ---- Phase 2: adjacency, flat-indexed over the contiguous matrix ----
    // Thread t owns fixed column group cg = t % 49 (u-vectors register-
    // resident; the scattered LDS happens exactly once). Flat float4 index
    // advances by TPB=392 = 8*49 per iteration, so cg never changes and
    // row += 8. Every warp's 32 lanes store 32 consecutive float4 = one
    // dense 512B run, regardless of row boundaries. 100% lane utilization.
    {
        const int cg = tid % NCG;
        int row      = tid / NCG;     // 0..7

        const float4 u0 = an_s[4 * cg + 0];
        const float4 u1 = an_s[4 * cg + 1];
        const float4 u2 = an_s[4 * cg + 2];
        const float4 u3 = an_s[4 * cg + 3];

        float4* __restrict__ adj4 =
            reinterpret_cast<float4*>(adj + (size_t)b * (NP * NP));

        for (int flat = tid; flat < NF4; flat += TPB, row += 8) {
            const float4 a = an_s[row];   // <=2 distinct rows per warp
            float4 r = make_float4(classify(dot4(a, u0)), classify(dot4(a, u1)),
                                   classify(dot4(a, u2)), classify(dot4(a, u3)));
            if ((row >> 2) == cg) {       // self-edge diagonal in this group
                const int c = row & 3;
                if      (c == 0) r.x = 0.f;
                else if (c == 1) r.y = 0.f;
                else if (c == 2) r.z = 0.f;
                else             r.w = 0.f;
            }
            __stcs(adj4 + flat, r);       // evict-first: write-once data
        }
    }
}

extern "C" void kernel_launch(void* const* d_in, const int* in_sizes, int n_in,
                              void* d_out, int out_size)
{
    const float* x  = (const float*)d_in[0];   // [B,1,28,28]
    const float* W1 = (const float*)d_in[1];   // [32,4]
    const float* b1 = (const float*)d_in[2];   // [32]
    const float* W2 = (const float*)d_in[3];   // [10,32]
    const float* b2 = (const float*)d_in[4];   // [10]

    const int B = in_sizes[0] / 784;           // 4096

    float* out = (float*)d_out;                // [B,10] first
    float* adj = (float*)d_out + (size_t)B * NCLS;  // then [B,196,196]

    quanv_graph_kernel<<<B, TPB>>>(x, W1, b1, W2, b2, out, adj);
}